// round 13
// baseline (speedup 1.0000x reference)
#include <cuda_runtime.h>

#define H_IN  192
#define W_IN  192
#define H_OUT 96
#define W_OUT 96
#define BATCH 1024
#define ROWS_PER_CTA 48   // 2 CTAs per image (top/bottom halves)

// 2 CTAs per batch image (grid 2048 -> ~2.8 waves at 5 CTAs/SM, small tail).
// Block (96, 4): threadIdx.x = output column w (fixed per thread -> all
// x-axis sampling math hoisted out of the loop), threadIdx.y strides the
// 48 output rows of this CTA's half. Consecutive lanes = consecutive w,
// so each tap LDG within a warp spans <= 2s*32*4 B <= 256 B (1-3 lines).
__global__ __launch_bounds__(384) void st_kernel(
    const float* __restrict__ x,       // [B, 1, 192, 192]
    const float* __restrict__ z_where, // [B, 3] = (s, tx, ty)
    float* __restrict__ out)           // [B, 1, 96, 96]
{
    const int b     = blockIdx.x >> 1;
    const int hbase = (blockIdx.x & 1) * ROWS_PER_CTA;

    const float s  = __ldg(&z_where[b * 3 + 0]);
    const float tx = __ldg(&z_where[b * 3 + 1]);
    const float ty = __ldg(&z_where[b * 3 + 2]);

    // ix = ((s*gx + tx + 1)*W_IN - 1)*0.5, gx = (2w+1)/W_OUT - 1, W_IN = 2*W_OUT
    //    = 2s*w + (s + 96*(tx + 1 - s) - 0.5); same form for iy (ay == ax).
    const float ax = 2.0f * s;
    const float bx = s + 96.0f * (tx + 1.0f - s) - 0.5f;
    const float by = s + 96.0f * (ty + 1.0f - s) - 0.5f;

    // ---- per-thread x-axis sampling data (loop-invariant) ----
    const int   w   = threadIdx.x;           // 0..95
    const float ix  = ax * (float)w + bx;
    const float fx  = floorf(ix);
    const int   x0  = (int)fx;
    const int   x1  = x0 + 1;
    const float wx1 = ix - fx;
    const bool  vx0 = (x0 >= 0) & (x0 < W_IN);
    const bool  vx1 = (x1 >= 0) & (x1 < W_IN);
    const int   xc0 = min(max(x0, 0), W_IN - 1);
    const int   xc1 = min(max(x1, 0), W_IN - 1);

    const float* img = x + (size_t)b * (H_IN * W_IN);
    float* o = out + (size_t)b * (H_OUT * W_OUT) + w;

    #pragma unroll
    for (int hh = threadIdx.y; hh < ROWS_PER_CTA; hh += 4) {
        const int   h   = hbase + hh;
        const float iy  = ax * (float)h + by;
        const float fy  = floorf(iy);
        const int   y0  = (int)fy;
        const int   y1  = y0 + 1;
        const float wy1 = iy - fy;
        const bool  vy0 = (y0 >= 0) & (y0 < H_IN);
        const bool  vy1 = (y1 >= 0) & (y1 < H_IN);
        const float* r0 = img + (size_t)min(max(y0, 0), H_IN - 1) * W_IN;
        const float* r1 = img + (size_t)min(max(y1, 0), H_IN - 1) * W_IN;

        const float v00 = (vy0 & vx0) ? __ldg(r0 + xc0) : 0.0f;
        const float v01 = (vy0 & vx1) ? __ldg(r0 + xc1) : 0.0f;
        const float v10 = (vy1 & vx0) ? __ldg(r1 + xc0) : 0.0f;
        const float v11 = (vy1 & vx1) ? __ldg(r1 + xc1) : 0.0f;

        // bilinear via lerp: 5 FMAs
        const float t0 = v00 + wx1 * (v01 - v00);
        const float t1 = v10 + wx1 * (v11 - v10);
        o[h * W_OUT] = t0 + wy1 * (t1 - t0);
    }
}

extern "C" void kernel_launch(void* const* d_in, const int* in_sizes, int n_in,
                              void* d_out, int out_size) {
    // Expected order per reference setup_inputs(): x [B*1*192*192], z_where [B*3].
    // Defensive: identify by element count.
    const float* x  = (const float*)d_in[0];
    const float* zw = (const float*)d_in[1];
    if (n_in >= 2 && in_sizes[0] == BATCH * 3) {  // swapped order
        x  = (const float*)d_in[1];
        zw = (const float*)d_in[0];
    }
    float* out = (float*)d_out;
    dim3 block(96, 4);
    st_kernel<<<BATCH * 2, block>>>(x, zw, out);
}

// round 16
// speedup vs baseline: 1.3067x; 1.3067x over previous
#include <cuda_runtime.h>

#define H_IN  192
#define W_IN  192
#define H_OUT 96
#define W_OUT 96
#define BATCH 1024
#define ROWS_PER_CTA 48   // 2 CTAs per image (top/bottom halves)

// Issue-bound fix (R13 profile: alu=35%, issue=57%, DRAM=21%):
//  - y-side sampling data (row byte-offsets + validity-masked weights)
//    precomputed ONCE per CTA into smem; inner loop reads one LDS.128
//    (warp-broadcast) instead of floor/cvt/clamp/setp per pixel.
//  - validity folded into weights; loads use clamped (always in-bounds)
//    addresses -> no predicated selects on the 4 taps.
// Layout unchanged: block (96,4), lane = output column w (warp tap span
// <= 256 B), 2 CTAs per image, full unroll of 12 row iterations.
__global__ __launch_bounds__(384) void st_kernel(
    const float* __restrict__ x,       // [B, 1, 192, 192]
    const float* __restrict__ z_where, // [B, 3] = (s, tx, ty)
    float* __restrict__ out)           // [B, 1, 96, 96]
{
    __shared__ float4 yrow[ROWS_PER_CTA];  // {byteoff_r0, byteoff_r1, wy0m, wy1m}

    const int b     = blockIdx.x >> 1;
    const int hbase = (blockIdx.x & 1) * ROWS_PER_CTA;

    const float s  = __ldg(&z_where[b * 3 + 0]);
    const float tx = __ldg(&z_where[b * 3 + 1]);
    const float ty = __ldg(&z_where[b * 3 + 2]);

    // ix = 2s*w + (s + 96*(tx + 1 - s) - 0.5); same affine form for iy.
    const float ax = 2.0f * s;
    const float bx = s + 96.0f * (tx + 1.0f - s) - 0.5f;
    const float by = s + 96.0f * (ty + 1.0f - s) - 0.5f;

    // ---- per-CTA y-side precompute (first 48 threads) ----
    const int tid = threadIdx.y * 96 + threadIdx.x;
    if (tid < ROWS_PER_CTA) {
        const int   h   = hbase + tid;
        const float iy  = ax * (float)h + by;
        const float fy  = floorf(iy);
        const int   y0  = (int)fy;
        const int   y1  = y0 + 1;
        const float wy1 = iy - fy;
        const float wy0 = 1.0f - wy1;
        const float m0  = ((y0 >= 0) & (y0 < H_IN)) ? wy0 : 0.0f;
        const float m1  = ((y1 >= 0) & (y1 < H_IN)) ? wy1 : 0.0f;
        const int   yo0 = min(max(y0, 0), H_IN - 1) * (W_IN * 4);
        const int   yo1 = min(max(y1, 0), H_IN - 1) * (W_IN * 4);
        yrow[tid] = make_float4(__int_as_float(yo0), __int_as_float(yo1), m0, m1);
    }

    // ---- per-thread x-side (loop-invariant) ----
    const int   w    = threadIdx.x;          // 0..95
    const float ix   = ax * (float)w + bx;
    const float fx   = floorf(ix);
    const int   x0   = (int)fx;
    const int   x1   = x0 + 1;
    const float wx1  = ix - fx;
    const float wx0m = ((x0 >= 0) & (x0 < W_IN)) ? (1.0f - wx1) : 0.0f;
    const float wx1m = ((x1 >= 0) & (x1 < W_IN)) ? wx1 : 0.0f;
    const int   xo0  = min(max(x0, 0), W_IN - 1) * 4;   // byte offset
    const int   xo1  = min(max(x1, 0), W_IN - 1) * 4;

    __syncthreads();

    const char* imgb = (const char*)(x + (size_t)b * (H_IN * W_IN));
    float* o = out + (size_t)b * (H_OUT * W_OUT)
                   + (hbase + threadIdx.y) * W_OUT + w;

    #pragma unroll
    for (int k = 0; k < ROWS_PER_CTA / 4; k++) {
        const float4 e   = yrow[threadIdx.y + 4 * k];   // broadcast LDS.128
        const int    yo0 = __float_as_int(e.x);
        const int    yo1 = __float_as_int(e.y);

        const float v00 = __ldg((const float*)(imgb + (yo0 + xo0)));
        const float v01 = __ldg((const float*)(imgb + (yo0 + xo1)));
        const float v10 = __ldg((const float*)(imgb + (yo1 + xo0)));
        const float v11 = __ldg((const float*)(imgb + (yo1 + xo1)));

        const float t0 = fmaf(v01, wx1m, v00 * wx0m);
        const float t1 = fmaf(v11, wx1m, v10 * wx0m);
        o[k * 4 * W_OUT] = fmaf(t1, e.w, t0 * e.z);
    }
}

extern "C" void kernel_launch(void* const* d_in, const int* in_sizes, int n_in,
                              void* d_out, int out_size) {
    // Expected order per reference setup_inputs(): x [B*1*192*192], z_where [B*3].
    // Defensive: identify by element count.
    const float* x  = (const float*)d_in[0];
    const float* zw = (const float*)d_in[1];
    if (n_in >= 2 && in_sizes[0] == BATCH * 3) {  // swapped order
        x  = (const float*)d_in[1];
        zw = (const float*)d_in[0];
    }
    float* out = (float*)d_out;
    dim3 block(96, 4);
    st_kernel<<<BATCH * 2, block>>>(x, zw, out);
}